// round 1
// baseline (speedup 1.0000x reference)
#include <cuda_runtime.h>
#include <cstdint>

// Problem constants (fixed shapes for this dataset)
#define BB   4
#define NN   50000
#define CIN  64
#define EE   800000
#define HALF 32
#define BN   (BB * NN)        // 200000 (exactly divisible by 64)

// ---------------- scratch (device globals; no allocation allowed) ----------
__device__ float g_hlin[BB * NN * HALF];   // [B, N, 32] projected x (no bias)
__device__ int   g_counts[NN];
__device__ int   g_offsets[NN + 1];
__device__ int   g_cursor[NN];
__device__ int2  g_csr[EE];                // .x = col, .y = bits(val)

// ---------------- zero counts ----------------------------------------------
__global__ void zero_counts_kernel() {
    int i = blockIdx.x * blockDim.x + threadIdx.x;
    if (i < NN) g_counts[i] = 0;
}

// ---------------- histogram of rows ----------------------------------------
__global__ void hist_kernel(const int* __restrict__ rows) {
    int e = blockIdx.x * blockDim.x + threadIdx.x;
    if (e < EE) atomicAdd(&g_counts[rows[e]], 1);
}

// ---------------- single-block exclusive scan over counts ------------------
__global__ void scan_kernel() {
    __shared__ int warp_sums[32];
    __shared__ int s_running;
    const int tid  = threadIdx.x;     // 1024 threads
    const int lane = tid & 31;
    const int wid  = tid >> 5;
    if (tid == 0) s_running = 0;
    __syncthreads();

    for (int base = 0; base < NN; base += 1024) {
        int i = base + tid;
        int v = (i < NN) ? g_counts[i] : 0;
        // inclusive scan within warp
        int x = v;
        #pragma unroll
        for (int d = 1; d < 32; d <<= 1) {
            int y = __shfl_up_sync(0xFFFFFFFFu, x, d);
            if (lane >= d) x += y;
        }
        if (lane == 31) warp_sums[wid] = x;
        __syncthreads();
        if (tid < 32) {
            int s = warp_sums[tid];
            #pragma unroll
            for (int d = 1; d < 32; d <<= 1) {
                int y = __shfl_up_sync(0xFFFFFFFFu, s, d);
                if (tid >= d) s += y;
            }
            warp_sums[tid] = s;   // inclusive warp prefix
        }
        __syncthreads();
        int wp   = (wid > 0) ? warp_sums[wid - 1] : 0;
        int incl = x + wp + s_running;
        if (i < NN) {
            int excl = incl - v;
            g_offsets[i] = excl;
            g_cursor[i]  = excl;
        }
        __syncthreads();
        if (tid == 1023) s_running = incl;
        __syncthreads();
    }
    if (tid == 0) g_offsets[NN] = s_running;   // == EE
}

// ---------------- CSR scatter -----------------------------------------------
__global__ void scatter_kernel(const int* __restrict__ rows,
                               const int* __restrict__ cols,
                               const float* __restrict__ vals) {
    int e = blockIdx.x * blockDim.x + threadIdx.x;
    if (e < EE) {
        int r = rows[e];
        int p = atomicAdd(&g_cursor[r], 1);
        g_csr[p] = make_int2(cols[e], __float_as_int(vals[e]));
    }
}

// ---------------- projection: h_lin = x @ Wlin^T ; out[:,32:] = x @ Weye^T + beye
// Block: 256 threads, tile = 64 nodes x 64 outputs, 4x4 register tile / thread.
__global__ __launch_bounds__(256) void proj_kernel(const float* __restrict__ x,
                                                   const float* __restrict__ Wlin,
                                                   const float* __restrict__ Weye,
                                                   const float* __restrict__ beye,
                                                   float* __restrict__ out) {
    __shared__ float xs[64][65];
    __shared__ float ws[64][65];
    const int tid   = threadIdx.x;
    const int node0 = blockIdx.x * 64;

    // Load combined W: rows 0..31 = Wlin, rows 32..63 = Weye
    for (int idx = tid; idx < 4096; idx += 256) {
        int r = idx >> 6, c = idx & 63;
        ws[r][c] = (r < 32) ? Wlin[r * 64 + c] : Weye[(r - 32) * 64 + c];
    }
    // Load 64-node x tile (float4 coalesced)
    const float4* xg = (const float4*)(x + (size_t)node0 * 64);
    for (int idx = tid; idx < 1024; idx += 256) {
        float4 v = xg[idx];
        int r = idx >> 4;
        int c = (idx & 15) << 2;
        xs[r][c] = v.x; xs[r][c + 1] = v.y; xs[r][c + 2] = v.z; xs[r][c + 3] = v.w;
    }
    __syncthreads();

    const int tx = tid & 15;   // node group: nodes tx*4 .. tx*4+3
    const int ty = tid >> 4;   // out group:  outs  ty*4 .. ty*4+3
    float acc[4][4] = {};

    #pragma unroll 8
    for (int c = 0; c < 64; ++c) {
        float a0 = xs[tx * 4 + 0][c], a1 = xs[tx * 4 + 1][c];
        float a2 = xs[tx * 4 + 2][c], a3 = xs[tx * 4 + 3][c];
        float w0 = ws[ty * 4 + 0][c], w1 = ws[ty * 4 + 1][c];
        float w2 = ws[ty * 4 + 2][c], w3 = ws[ty * 4 + 3][c];
        acc[0][0] += a0 * w0; acc[0][1] += a0 * w1; acc[0][2] += a0 * w2; acc[0][3] += a0 * w3;
        acc[1][0] += a1 * w0; acc[1][1] += a1 * w1; acc[1][2] += a1 * w2; acc[1][3] += a1 * w3;
        acc[2][0] += a2 * w0; acc[2][1] += a2 * w1; acc[2][2] += a2 * w2; acc[2][3] += a2 * w3;
        acc[3][0] += a3 * w0; acc[3][1] += a3 * w1; acc[3][2] += a3 * w2; acc[3][3] += a3 * w3;
    }

    const int o0 = ty * 4;
    if (o0 < 32) {
        // lin half -> scratch (bias added in gather)
        #pragma unroll
        for (int i = 0; i < 4; ++i) {
            int node = node0 + tx * 4 + i;
            float4 v = make_float4(acc[i][0], acc[i][1], acc[i][2], acc[i][3]);
            *(float4*)&g_hlin[(size_t)node * 32 + o0] = v;
        }
    } else {
        float b0 = beye[o0 - 32], b1 = beye[o0 - 31], b2 = beye[o0 - 30], b3 = beye[o0 - 29];
        #pragma unroll
        for (int i = 0; i < 4; ++i) {
            int node = node0 + tx * 4 + i;
            float4 v = make_float4(acc[i][0] + b0, acc[i][1] + b1,
                                   acc[i][2] + b2, acc[i][3] + b3);
            *(float4*)&out[(size_t)node * 64 + o0] = v;
        }
    }
}

// ---------------- gather: out[b,n,0:32] = b_lin + sum_e val * h_lin[b, col, :]
// One warp per (n, b); lane = channel. 4-way unrolled for MLP.
__global__ __launch_bounds__(256) void gather_kernel(const float* __restrict__ blin,
                                                     float* __restrict__ out) {
    int gw   = (blockIdx.x * blockDim.x + threadIdx.x) >> 5;
    int lane = threadIdx.x & 31;
    if (gw >= BN) return;
    int n = gw >> 2;
    int b = gw & 3;

    int s = g_offsets[n];
    int t = g_offsets[n + 1];

    const float* hb = g_hlin + (size_t)b * NN * 32;

    float acc0 = blin[lane], acc1 = 0.f, acc2 = 0.f, acc3 = 0.f;
    int e = s;
    for (; e + 4 <= t; e += 4) {
        int2 p0 = g_csr[e + 0];
        int2 p1 = g_csr[e + 1];
        int2 p2 = g_csr[e + 2];
        int2 p3 = g_csr[e + 3];
        acc0 += __int_as_float(p0.y) * hb[(size_t)p0.x * 32 + lane];
        acc1 += __int_as_float(p1.y) * hb[(size_t)p1.x * 32 + lane];
        acc2 += __int_as_float(p2.y) * hb[(size_t)p2.x * 32 + lane];
        acc3 += __int_as_float(p3.y) * hb[(size_t)p3.x * 32 + lane];
    }
    for (; e < t; ++e) {
        int2 p = g_csr[e];
        acc0 += __int_as_float(p.y) * hb[(size_t)p.x * 32 + lane];
    }
    out[((size_t)b * NN + n) * 64 + lane] = (acc0 + acc1) + (acc2 + acc3);
}

// ---------------- launch -----------------------------------------------------
extern "C" void kernel_launch(void* const* d_in, const int* in_sizes, int n_in,
                              void* d_out, int out_size) {
    const float* x    = (const float*)d_in[0];
    const float* vals = (const float*)d_in[1];
    const float* Wlin = (const float*)d_in[2];
    const float* blin = (const float*)d_in[3];
    const float* Weye = (const float*)d_in[4];
    const float* beye = (const float*)d_in[5];
    const int*   rows = (const int*)d_in[6];
    const int*   cols = (const int*)d_in[7];
    float* out = (float*)d_out;

    // CSR build
    zero_counts_kernel<<<(NN + 255) / 256, 256>>>();
    hist_kernel<<<(EE + 255) / 256, 256>>>(rows);
    scan_kernel<<<1, 1024>>>();
    scatter_kernel<<<(EE + 255) / 256, 256>>>(rows, cols, vals);

    // Dense projection (independent of CSR chain but same stream is fine)
    proj_kernel<<<BN / 64, 256>>>(x, Wlin, Weye, beye, out);

    // Sparse gather into lin half
    gather_kernel<<<(BN * 32 + 255) / 256, 256>>>(blin, out);
}

// round 2
// speedup vs baseline: 1.2928x; 1.2928x over previous
#include <cuda_runtime.h>
#include <cstdint>

// Problem constants (fixed shapes for this dataset)
#define BB   4
#define NN   50000
#define CIN  64
#define EE   800000
#define HALF 32
#define BN   (BB * NN)           // 200000

#define SCAT_BLOCKS 782          // ceil(EE / (128*8))
#define PROJ_BLOCKS 3125         // BN / 64
#define SCANB_BLOCKS 49          // ceil(NN/1024)

// ---------------- scratch (device globals; no allocation allowed) ----------
__device__ float g_hlin[NN * 128];     // [n][b*32 + ch]  (25.6 MB, L2-resident)
__device__ int   g_counts[NN];
__device__ int   g_offsets[NN + 1];
__device__ int   g_cursor[NN];
__device__ int2  g_csr[EE];            // .x = col, .y = bits(val)
__device__ int   g_blocksums[64];

// ---------------- f32x2 helpers --------------------------------------------
__device__ __forceinline__ void ffma2(unsigned long long& d,
                                      unsigned long long a,
                                      unsigned long long b) {
    asm("fma.rn.f32x2 %0, %1, %2, %0;" : "+l"(d) : "l"(a), "l"(b));
}
__device__ __forceinline__ unsigned long long dup2(float v) {
    unsigned long long d;
    unsigned u = __float_as_uint(v);
    asm("mov.b64 %0, {%1, %1};" : "=l"(d) : "r"(u));
    return d;
}

// ---------------- zero counts ----------------------------------------------
__global__ void zero_counts_kernel() {
    int i = blockIdx.x * blockDim.x + threadIdx.x;
    if (i < NN) g_counts[i] = 0;
}

// ---------------- histogram of rows (4 edges / thread) ----------------------
__global__ __launch_bounds__(256) void hist_kernel(const int* __restrict__ rows) {
    int e0 = blockIdx.x * 1024 + threadIdx.x;
    #pragma unroll
    for (int k = 0; k < 4; ++k) {
        int e = e0 + k * 256;
        if (e < EE) atomicAdd(&g_counts[rows[e]], 1);
    }
}

// ---------------- scan phase A: per-1024-chunk sums --------------------------
__global__ __launch_bounds__(1024) void scanA_kernel() {
    __shared__ int ws[32];
    const int tid = threadIdx.x, lane = tid & 31, wid = tid >> 5;
    int i = blockIdx.x * 1024 + tid;
    int v = (i < NN) ? g_counts[i] : 0;
    #pragma unroll
    for (int d = 16; d > 0; d >>= 1) v += __shfl_down_sync(0xFFFFFFFFu, v, d);
    if (lane == 0) ws[wid] = v;
    __syncthreads();
    if (tid < 32) {
        int s = ws[tid];
        #pragma unroll
        for (int d = 16; d > 0; d >>= 1) s += __shfl_down_sync(0xFFFFFFFFu, s, d);
        if (tid == 0) g_blocksums[blockIdx.x] = s;
    }
}

// ---------------- scan phase B: local scan + base ----------------------------
__global__ __launch_bounds__(1024) void scanB_kernel() {
    __shared__ int ssum[64];
    __shared__ int wsum[32];
    const int tid = threadIdx.x, lane = tid & 31, wid = tid >> 5;
    const int j = blockIdx.x;
    if (tid < SCANB_BLOCKS) ssum[tid] = g_blocksums[tid];
    __syncthreads();
    int base = 0;
    for (int k = 0; k < j; ++k) base += ssum[k];

    int i = j * 1024 + tid;
    int v = (i < NN) ? g_counts[i] : 0;
    int x = v;
    #pragma unroll
    for (int d = 1; d < 32; d <<= 1) {
        int y = __shfl_up_sync(0xFFFFFFFFu, x, d);
        if (lane >= d) x += y;
    }
    if (lane == 31) wsum[wid] = x;
    __syncthreads();
    if (tid < 32) {
        int s = wsum[tid];
        #pragma unroll
        for (int d = 1; d < 32; d <<= 1) {
            int y = __shfl_up_sync(0xFFFFFFFFu, s, d);
            if (tid >= d) s += y;
        }
        wsum[tid] = s;
    }
    __syncthreads();
    int incl = x + (wid ? wsum[wid - 1] : 0) + base;
    if (i < NN) {
        int excl = incl - v;
        g_offsets[i] = excl;
        g_cursor[i]  = excl;
    }
    if (j == 0 && tid == 0) g_offsets[NN] = EE;
}

// ---------------- fused: CSR scatter (blocks < SCAT_BLOCKS) + projection -----
// proj: 64-node x 64-out tile, 128 threads, f32x2 packed FMA.
//   thread: 4 nodes {tx, tx+16, tx+32, tx+48} x 8 outs [ty*8, ty*8+8)
__global__ __launch_bounds__(128) void fused_scatter_proj_kernel(
    const int*   __restrict__ rows,
    const int*   __restrict__ cols,
    const float* __restrict__ vals,
    const float* __restrict__ x,
    const float* __restrict__ Wlin,
    const float* __restrict__ Weye,
    const float* __restrict__ beye,
    float*       __restrict__ out)
{
    __shared__ float xs[64][65];   // [node][c]
    __shared__ float wt[64][66];   // [c][o]  (o pairs contiguous)

    const int tid = threadIdx.x;

    if (blockIdx.x < SCAT_BLOCKS) {
        // ---- scatter: 8 edges / thread ----
        int e0 = blockIdx.x * 1024 + tid;
        #pragma unroll
        for (int k = 0; k < 8; ++k) {
            int e = e0 + k * 128;
            if (e < EE) {
                int r = rows[e];
                int p = atomicAdd(&g_cursor[r], 1);
                g_csr[p] = make_int2(cols[e], __float_as_int(vals[e]));
            }
        }
        return;
    }

    // ---- projection ----
    const int node0 = (blockIdx.x - SCAT_BLOCKS) * 64;   // global bn row base

    // load x tile: 64 rows x 64 ch = 1024 float4
    const float4* xg = (const float4*)(x + (size_t)node0 * 64);
    for (int idx = tid; idx < 1024; idx += 128) {
        float4 v = xg[idx];
        int node = idx >> 4;
        int c = (idx & 15) << 2;
        xs[node][c] = v.x; xs[node][c + 1] = v.y;
        xs[node][c + 2] = v.z; xs[node][c + 3] = v.w;
    }
    // load W transposed: wt[c][o], rows 0..31 = Wlin, 32..63 = Weye
    for (int idx = tid; idx < 4096; idx += 128) {
        int o = idx >> 6, c = idx & 63;
        wt[c][o] = (o < 32) ? Wlin[o * 64 + c] : Weye[(o - 32) * 64 + c];
    }
    __syncthreads();

    const int tx = tid & 15;   // node lane
    const int ty = tid >> 4;   // out group (0..7), outs ty*8 .. ty*8+7

    unsigned long long acc[4][4];
    #pragma unroll
    for (int i = 0; i < 4; ++i)
        #pragma unroll
        for (int j = 0; j < 4; ++j) acc[i][j] = 0ull;

    #pragma unroll 8
    for (int c = 0; c < 64; ++c) {
        unsigned long long a[4], w[4];
        #pragma unroll
        for (int i = 0; i < 4; ++i) a[i] = dup2(xs[tx + 16 * i][c]);
        #pragma unroll
        for (int j = 0; j < 4; ++j)
            w[j] = *(const unsigned long long*)&wt[c][ty * 8 + 2 * j];
        #pragma unroll
        for (int i = 0; i < 4; ++i)
            #pragma unroll
            for (int j = 0; j < 4; ++j) ffma2(acc[i][j], a[i], w[j]);
    }

    // epilogue
    const int och = ty * 8;                  // first output channel of this thread
    if (och < 32) {
        // lin half -> g_hlin[n*128 + b*32 + ch]
        #pragma unroll
        for (int i = 0; i < 4; ++i) {
            int bn = node0 + tx + 16 * i;
            int b = bn / NN;
            int n = bn - b * NN;
            float* dst = &g_hlin[(size_t)n * 128 + b * 32 + och];
            float4 v0, v1;
            v0.x = __uint_as_float((unsigned)(acc[i][0]));
            v0.y = __uint_as_float((unsigned)(acc[i][0] >> 32));
            v0.z = __uint_as_float((unsigned)(acc[i][1]));
            v0.w = __uint_as_float((unsigned)(acc[i][1] >> 32));
            v1.x = __uint_as_float((unsigned)(acc[i][2]));
            v1.y = __uint_as_float((unsigned)(acc[i][2] >> 32));
            v1.z = __uint_as_float((unsigned)(acc[i][3]));
            v1.w = __uint_as_float((unsigned)(acc[i][3] >> 32));
            *(float4*)dst = v0;
            *(float4*)(dst + 4) = v1;
        }
    } else {
        float be[8];
        #pragma unroll
        for (int k = 0; k < 8; ++k) be[k] = beye[och - 32 + k];
        #pragma unroll
        for (int i = 0; i < 4; ++i) {
            int bn = node0 + tx + 16 * i;
            float* dst = &out[(size_t)bn * 64 + och];
            float4 v0, v1;
            v0.x = __uint_as_float((unsigned)(acc[i][0]))       + be[0];
            v0.y = __uint_as_float((unsigned)(acc[i][0] >> 32)) + be[1];
            v0.z = __uint_as_float((unsigned)(acc[i][1]))       + be[2];
            v0.w = __uint_as_float((unsigned)(acc[i][1] >> 32)) + be[3];
            v1.x = __uint_as_float((unsigned)(acc[i][2]))       + be[4];
            v1.y = __uint_as_float((unsigned)(acc[i][2] >> 32)) + be[5];
            v1.z = __uint_as_float((unsigned)(acc[i][3]))       + be[6];
            v1.w = __uint_as_float((unsigned)(acc[i][3] >> 32)) + be[7];
            *(float4*)dst = v0;
            *(float4*)(dst + 4) = v1;
        }
    }
}

// ---------------- gather: one warp per node, all 4 batches -------------------
__global__ __launch_bounds__(256) void gather_kernel(const float* __restrict__ blin,
                                                     float* __restrict__ out) {
    int n    = (blockIdx.x * blockDim.x + threadIdx.x) >> 5;
    int lane = threadIdx.x & 31;
    if (n >= NN) return;

    int s = g_offsets[n];
    int t = g_offsets[n + 1];

    float a0 = 0.f, a1 = 0.f, a2 = 0.f, a3 = 0.f;
    int e = s;
    for (; e + 2 <= t; e += 2) {
        int2 p0 = g_csr[e];
        int2 p1 = g_csr[e + 1];
        const float* h0 = g_hlin + (size_t)p0.x * 128 + lane;
        const float* h1 = g_hlin + (size_t)p1.x * 128 + lane;
        float u0 = h0[0], u1 = h0[32], u2 = h0[64], u3 = h0[96];
        float v0 = h1[0], v1 = h1[32], v2 = h1[64], v3 = h1[96];
        float s0 = __int_as_float(p0.y);
        float s1 = __int_as_float(p1.y);
        a0 += s0 * u0; a1 += s0 * u1; a2 += s0 * u2; a3 += s0 * u3;
        a0 += s1 * v0; a1 += s1 * v1; a2 += s1 * v2; a3 += s1 * v3;
    }
    if (e < t) {
        int2 p = g_csr[e];
        const float* h = g_hlin + (size_t)p.x * 128 + lane;
        float sv = __int_as_float(p.y);
        a0 += sv * h[0]; a1 += sv * h[32]; a2 += sv * h[64]; a3 += sv * h[96];
    }

    float bl = blin[lane];
    out[((size_t)0 * NN + n) * 64 + lane] = a0 + bl;
    out[((size_t)1 * NN + n) * 64 + lane] = a1 + bl;
    out[((size_t)2 * NN + n) * 64 + lane] = a2 + bl;
    out[((size_t)3 * NN + n) * 64 + lane] = a3 + bl;
}

// ---------------- launch -----------------------------------------------------
extern "C" void kernel_launch(void* const* d_in, const int* in_sizes, int n_in,
                              void* d_out, int out_size) {
    const float* x    = (const float*)d_in[0];
    const float* vals = (const float*)d_in[1];
    const float* Wlin = (const float*)d_in[2];
    const float* blin = (const float*)d_in[3];
    const float* Weye = (const float*)d_in[4];
    const float* beye = (const float*)d_in[5];
    const int*   rows = (const int*)d_in[6];
    const int*   cols = (const int*)d_in[7];
    float* out = (float*)d_out;
    (void)in_sizes; (void)n_in; (void)out_size;

    zero_counts_kernel<<<(NN + 255) / 256, 256>>>();
    hist_kernel<<<SCAT_BLOCKS, 256>>>(rows);
    scanA_kernel<<<SCANB_BLOCKS, 1024>>>();
    scanB_kernel<<<SCANB_BLOCKS, 1024>>>();
    fused_scatter_proj_kernel<<<SCAT_BLOCKS + PROJ_BLOCKS, 128>>>(
        rows, cols, vals, x, Wlin, Weye, beye, out);
    gather_kernel<<<(NN * 32 + 255) / 256, 256>>>(blin, out);
}

// round 3
// speedup vs baseline: 1.9736x; 1.5266x over previous
#include <cuda_runtime.h>
#include <cuda_fp16.h>
#include <cstdint>

// Problem constants (fixed shapes for this dataset)
#define BB   4
#define NN   50000
#define CIN  64
#define EE   800000
#define HALF 32
#define BN   (BB * NN)           // 200000

#define SCAT_BLOCKS 782          // ceil(EE / (128*8))
#define PROJ_BLOCKS 3125         // NN / 16
#define SCANB_BLOCKS 49          // ceil(NN/1024)

// ---------------- scratch (device globals; no allocation allowed) ----------
__device__ __half g_hlin[NN * 128];    // [n][ch][b]  half, 12.8 MB (L2-resident)
__device__ int    g_counts[NN];
__device__ int    g_offsets[NN + 1];
__device__ int    g_cursor[NN];
__device__ int2   g_csr[EE];           // .x = col, .y = bits(val)
__device__ int    g_blocksums[64];

// ---------------- f32x2 helpers --------------------------------------------
__device__ __forceinline__ void ffma2(unsigned long long& d,
                                      unsigned long long a,
                                      unsigned long long b) {
    asm("fma.rn.f32x2 %0, %1, %2, %0;" : "+l"(d) : "l"(a), "l"(b));
}
__device__ __forceinline__ unsigned long long dup2(float v) {
    unsigned long long d;
    unsigned u = __float_as_uint(v);
    asm("mov.b64 %0, {%1, %1};" : "=l"(d) : "r"(u));
    return d;
}
__device__ __forceinline__ float lo32(unsigned long long v) {
    return __uint_as_float((unsigned)v);
}
__device__ __forceinline__ float hi32(unsigned long long v) {
    return __uint_as_float((unsigned)(v >> 32));
}

// ---------------- histogram of rows (int4 vectorized) ------------------------
__global__ __launch_bounds__(256) void hist_kernel(const int4* __restrict__ rows4) {
    int i = blockIdx.x * blockDim.x + threadIdx.x;
    if (i < EE / 4) {
        int4 r = rows4[i];
        atomicAdd(&g_counts[r.x], 1);
        atomicAdd(&g_counts[r.y], 1);
        atomicAdd(&g_counts[r.z], 1);
        atomicAdd(&g_counts[r.w], 1);
    }
}

// ---------------- scan phase A: per-1024-chunk sums --------------------------
__global__ __launch_bounds__(1024) void scanA_kernel() {
    __shared__ int ws[32];
    const int tid = threadIdx.x, lane = tid & 31, wid = tid >> 5;
    int i = blockIdx.x * 1024 + tid;
    int v = (i < NN) ? g_counts[i] : 0;
    #pragma unroll
    for (int d = 16; d > 0; d >>= 1) v += __shfl_down_sync(0xFFFFFFFFu, v, d);
    if (lane == 0) ws[wid] = v;
    __syncthreads();
    if (tid < 32) {
        int s = (tid < 32) ? ws[tid] : 0;
        #pragma unroll
        for (int d = 16; d > 0; d >>= 1) s += __shfl_down_sync(0xFFFFFFFFu, s, d);
        if (tid == 0) g_blocksums[blockIdx.x] = s;
    }
}

// ---------------- scan phase B: local scan + base ----------------------------
__global__ __launch_bounds__(1024) void scanB_kernel() {
    __shared__ int ssum[64];
    __shared__ int wsum[32];
    const int tid = threadIdx.x, lane = tid & 31, wid = tid >> 5;
    const int j = blockIdx.x;
    if (tid < SCANB_BLOCKS) ssum[tid] = g_blocksums[tid];
    __syncthreads();
    int base = 0;
    for (int k = 0; k < j; ++k) base += ssum[k];

    int i = j * 1024 + tid;
    int v = (i < NN) ? g_counts[i] : 0;
    int x = v;
    #pragma unroll
    for (int d = 1; d < 32; d <<= 1) {
        int y = __shfl_up_sync(0xFFFFFFFFu, x, d);
        if (lane >= d) x += y;
    }
    if (lane == 31) wsum[wid] = x;
    __syncthreads();
    if (tid < 32) {
        int s = wsum[tid];
        #pragma unroll
        for (int d = 1; d < 32; d <<= 1) {
            int y = __shfl_up_sync(0xFFFFFFFFu, s, d);
            if (tid >= d) s += y;
        }
        wsum[tid] = s;
    }
    __syncthreads();
    int incl = x + (wid ? wsum[wid - 1] : 0) + base;
    if (i < NN) {
        int excl = incl - v;
        g_offsets[i] = excl;
        g_cursor[i]  = excl;
    }
    if (j == 0 && tid == 0) g_offsets[NN] = EE;
}

// ---------------- fused: CSR scatter (blocks < SCAT_BLOCKS) + projection -----
// proj tile: 16 nodes x 4 batches x 64 outs. 128 threads, f32x2 packed FMA.
//   tx = node (0..15), ty = out octet (0..7); acc[b][chpair]
__global__ __launch_bounds__(128) void fused_scatter_proj_kernel(
    const int*   __restrict__ rows,
    const int*   __restrict__ cols,
    const float* __restrict__ vals,
    const float* __restrict__ x,
    const float* __restrict__ Wlin,
    const float* __restrict__ Weye,
    const float* __restrict__ beye,
    float*       __restrict__ out)
{
    __shared__ float xs[64][65];   // [b*16+node][c]
    __shared__ float wt[64][66];   // [c][o]  (o pairs contiguous)

    const int tid = threadIdx.x;

    if (blockIdx.x < SCAT_BLOCKS) {
        // ---- scatter: 8 edges / thread ----
        int e0 = blockIdx.x * 1024 + tid;
        #pragma unroll
        for (int k = 0; k < 8; ++k) {
            int e = e0 + k * 128;
            if (e < EE) {
                int r = rows[e];
                int p = atomicAdd(&g_cursor[r], 1);
                g_csr[p] = make_int2(cols[e], __float_as_int(vals[e]));
            }
        }
        return;
    }

    // ---- projection ----
    const int node0 = (blockIdx.x - SCAT_BLOCKS) * 16;   // node base (0..49984)

    // load x tile: 64 rows (4 batches x 16 nodes) x 64 ch, float4 coalesced
    for (int idx = tid; idx < 1024; idx += 128) {
        int row  = idx >> 4;            // 0..63
        int b    = row >> 4;
        int node = row & 15;
        int c    = (idx & 15) << 2;
        float4 v = *(const float4*)(x + ((size_t)(b * NN + node0 + node)) * 64 + c);
        xs[row][c] = v.x; xs[row][c + 1] = v.y;
        xs[row][c + 2] = v.z; xs[row][c + 3] = v.w;
    }
    // load W transposed: wt[c][o], o 0..31 = Wlin, 32..63 = Weye
    for (int idx = tid; idx < 4096; idx += 128) {
        int o = idx >> 6, c = idx & 63;
        wt[c][o] = (o < 32) ? Wlin[o * 64 + c] : Weye[(o - 32) * 64 + c];
    }
    __syncthreads();

    const int tx = tid & 15;   // node lane
    const int ty = tid >> 4;   // out octet (0..7), outs ty*8 .. ty*8+7

    unsigned long long acc[4][4];
    #pragma unroll
    for (int b = 0; b < 4; ++b)
        #pragma unroll
        for (int j = 0; j < 4; ++j) acc[b][j] = 0ull;

    #pragma unroll 8
    for (int c = 0; c < 64; ++c) {
        unsigned long long a[4], w[4];
        #pragma unroll
        for (int b = 0; b < 4; ++b) a[b] = dup2(xs[b * 16 + tx][c]);
        #pragma unroll
        for (int j = 0; j < 4; ++j)
            w[j] = *(const unsigned long long*)&wt[c][ty * 8 + 2 * j];
        #pragma unroll
        for (int b = 0; b < 4; ++b)
            #pragma unroll
            for (int j = 0; j < 4; ++j) ffma2(acc[b][j], a[b], w[j]);
    }

    const int n   = node0 + tx;
    const int och = ty * 8;
    if (och < 32) {
        // lin half -> g_hlin[n][ch][b] as packed 4-half uint2 per channel
        #pragma unroll
        for (int j = 0; j < 4; ++j) {
            int ch = och + 2 * j;
            __half2 lo01 = __floats2half2_rn(lo32(acc[0][j]), lo32(acc[1][j]));
            __half2 lo23 = __floats2half2_rn(lo32(acc[2][j]), lo32(acc[3][j]));
            __half2 hi01 = __floats2half2_rn(hi32(acc[0][j]), hi32(acc[1][j]));
            __half2 hi23 = __floats2half2_rn(hi32(acc[2][j]), hi32(acc[3][j]));
            uint2 u0, u1;
            u0.x = *(unsigned*)&lo01; u0.y = *(unsigned*)&lo23;
            u1.x = *(unsigned*)&hi01; u1.y = *(unsigned*)&hi23;
            *(uint2*)&g_hlin[(size_t)n * 128 + ch * 4]       = u0;
            *(uint2*)&g_hlin[(size_t)n * 128 + (ch + 1) * 4] = u1;
        }
    } else {
        float be[8];
        #pragma unroll
        for (int k = 0; k < 8; ++k) be[k] = beye[och - 32 + k];
        #pragma unroll
        for (int b = 0; b < 4; ++b) {
            float* dst = &out[((size_t)b * NN + n) * 64 + och];
            float4 v0, v1;
            v0.x = lo32(acc[b][0]) + be[0];
            v0.y = hi32(acc[b][0]) + be[1];
            v0.z = lo32(acc[b][1]) + be[2];
            v0.w = hi32(acc[b][1]) + be[3];
            v1.x = lo32(acc[b][2]) + be[4];
            v1.y = hi32(acc[b][2]) + be[5];
            v1.z = lo32(acc[b][3]) + be[6];
            v1.w = hi32(acc[b][3]) + be[7];
            *(float4*)dst = v0;
            *(float4*)(dst + 4) = v1;
        }
    }
}

// ---------------- gather: one warp per node, all 4 batches, fp16 h ----------
__global__ __launch_bounds__(256) void gather_kernel(const float* __restrict__ blin,
                                                     float* __restrict__ out) {
    int n    = (blockIdx.x * blockDim.x + threadIdx.x) >> 5;
    int lane = threadIdx.x & 31;
    if (n >= NN) return;

    int s = g_offsets[n];
    int t = g_offsets[n + 1];

    float a0 = 0.f, a1 = 0.f, a2 = 0.f, a3 = 0.f;
    int e = s;
    for (; e + 2 <= t; e += 2) {
        int2 p0 = g_csr[e];
        int2 p1 = g_csr[e + 1];
        uint2 q0 = *(const uint2*)(g_hlin + (size_t)p0.x * 128 + lane * 4);
        uint2 q1 = *(const uint2*)(g_hlin + (size_t)p1.x * 128 + lane * 4);
        float s0 = __int_as_float(p0.y);
        float s1 = __int_as_float(p1.y);
        float2 u01 = __half22float2(*(__half2*)&q0.x);
        float2 u23 = __half22float2(*(__half2*)&q0.y);
        float2 v01 = __half22float2(*(__half2*)&q1.x);
        float2 v23 = __half22float2(*(__half2*)&q1.y);
        a0 += s0 * u01.x; a1 += s0 * u01.y; a2 += s0 * u23.x; a3 += s0 * u23.y;
        a0 += s1 * v01.x; a1 += s1 * v01.y; a2 += s1 * v23.x; a3 += s1 * v23.y;
    }
    if (e < t) {
        int2 p = g_csr[e];
        uint2 q = *(const uint2*)(g_hlin + (size_t)p.x * 128 + lane * 4);
        float sv = __int_as_float(p.y);
        float2 u01 = __half22float2(*(__half2*)&q.x);
        float2 u23 = __half22float2(*(__half2*)&q.y);
        a0 += sv * u01.x; a1 += sv * u01.y; a2 += sv * u23.x; a3 += sv * u23.y;
    }

    float bl = blin[lane];
    out[((size_t)0 * NN + n) * 64 + lane] = a0 + bl;
    out[((size_t)1 * NN + n) * 64 + lane] = a1 + bl;
    out[((size_t)2 * NN + n) * 64 + lane] = a2 + bl;
    out[((size_t)3 * NN + n) * 64 + lane] = a3 + bl;
}

// ---------------- launch -----------------------------------------------------
extern "C" void kernel_launch(void* const* d_in, const int* in_sizes, int n_in,
                              void* d_out, int out_size) {
    const float* x    = (const float*)d_in[0];
    const float* vals = (const float*)d_in[1];
    const float* Wlin = (const float*)d_in[2];
    const float* blin = (const float*)d_in[3];
    const float* Weye = (const float*)d_in[4];
    const float* beye = (const float*)d_in[5];
    const int*   rows = (const int*)d_in[6];
    const int*   cols = (const int*)d_in[7];
    float* out = (float*)d_out;
    (void)in_sizes; (void)n_in; (void)out_size;

    void* counts_ptr = nullptr;
    cudaGetSymbolAddress(&counts_ptr, g_counts);
    cudaMemsetAsync(counts_ptr, 0, NN * sizeof(int));

    hist_kernel<<<(EE / 4 + 255) / 256, 256>>>((const int4*)rows);
    scanA_kernel<<<SCANB_BLOCKS, 1024>>>();
    scanB_kernel<<<SCANB_BLOCKS, 1024>>>();
    fused_scatter_proj_kernel<<<SCAT_BLOCKS + PROJ_BLOCKS, 128>>>(
        rows, cols, vals, x, Wlin, Weye, beye, out);
    gather_kernel<<<(NN * 32 + 255) / 256, 256>>>(blin, out);
}